// round 10
// baseline (speedup 1.0000x reference)
#include <cuda_runtime.h>
#include <cuda_fp16.h>
#include <cstdint>

// Problem constants
static const int E   = 8;
static const int HID = 2048;
static const int ITR = 1408;
static const int MPE = 1024;

// GEMM tiling
static const int BM  = 128;   // M rows per CTA
static const int BNR = 256;   // B-tile rows per CTA (MODE0: 128 out cols x {gate,up})
static const int BK  = 32;    // K elems per stage
static const int NT  = 512;   // 16 warps
static const int SST = 20;    // smem row stride (words): 16 data + 4 pad, conflict-free frags
static const int AST = BM * SST;    // 2560 words
static const int BST = BNR * SST;   // 5120 words
static const int SMEM_BYTES = 2 * (AST + BST) * 4;  // 61440

// fp16 activations (hs packed once; g_dn produced by GEMM1)
__device__ __half g_a1[(size_t)E * MPE * HID];
__device__ __half g_dn[(size_t)E * MPE * ITR];

__device__ __forceinline__ uint32_t s2u(const void* p) {
    uint32_t a;
    asm("{ .reg .u64 t; cvta.to.shared.u64 t, %1; cvt.u32.u64 %0, t; }" : "=r"(a) : "l"(p));
    return a;
}
__device__ __forceinline__ void cp16(uint32_t dst, const void* src) {
    asm volatile("cp.async.cg.shared.global [%0], [%1], 16;" :: "r"(dst), "l"(src) : "memory");
}
__device__ __forceinline__ void mma16(float* c, const uint32_t* a, const uint32_t* b) {
    asm volatile(
        "mma.sync.aligned.m16n8k16.row.col.f32.f16.f16.f32 "
        "{%0,%1,%2,%3}, {%4,%5,%6,%7}, {%8,%9}, {%0,%1,%2,%3};\n"
        : "+f"(c[0]), "+f"(c[1]), "+f"(c[2]), "+f"(c[3])
        : "r"(a[0]), "r"(a[1]), "r"(a[2]), "r"(a[3]), "r"(b[0]), "r"(b[1]));
}
__device__ __forceinline__ uint32_t pack2(float x, float y) {
    __half2 h = __floats2half2_rn(x, y);
    return *(uint32_t*)&h;
}

// ---------------- pack hs -> fp16 (weights converted in-GEMM now) ------------
__global__ void __launch_bounds__(256)
pack_hs(const float* __restrict__ hs) {
    const size_t total = (size_t)E * MPE * (HID / 4);
    size_t i = (size_t)blockIdx.x * blockDim.x + threadIdx.x;
    const size_t step = (size_t)gridDim.x * blockDim.x;
    for (; i < total; i += step) {
        float4 v = ((const float4*)hs)[i];
        ((__half2*)g_a1)[2 * i]     = __floats2half2_rn(v.x, v.y);
        ((__half2*)g_a1)[2 * i + 1] = __floats2half2_rn(v.z, v.w);
    }
}

// ---------------- fused GEMM (fp16 mma, fp32 acc, in-kernel weight dequant) --
// MODE 0: gate_up (K=2048) + silu*up -> g_dn.  B rows interleaved gate/up.
// MODE 1: down    (K=1408) -> Out (fp32).
template <int MODE>
__global__ void __launch_bounds__(NT, 1)
moe_gemm(const float* __restrict__ Wg, const float* __restrict__ Sg,
         float* __restrict__ Out) {
    constexpr int K  = (MODE == 0) ? HID : ITR;
    constexpr int KT = K / BK;                           // 64 / 44
    constexpr int KB = K / 128;                          // 16 / 11
    constexpr int NWROWS = (MODE == 0) ? 2 * ITR : HID;

    extern __shared__ float sm[];
    const uint32_t sb = s2u(sm);
    const int tid = threadIdx.x, wid = tid >> 5, lane = tid & 31;
    const int g = lane >> 2, tg = lane & 3;
    const int e = blockIdx.z, m0 = blockIdx.y * BM, nb = blockIdx.x;

    const __half* Ag = ((MODE == 0) ? g_a1 : g_dn) + ((size_t)e * MPE + m0) * K;
    const float*  W  = Wg + (size_t)e * NWROWS * K;
    const float*  S  = Sg + (size_t)e * (NWROWS / 128) * KB;

    // A (fp16, cp.async): 512 chunks of 16B; 1 per thread
    const int ar = tid >> 2, ac = tid & 3;
    const __half* aptr = Ag + (size_t)ar * K + ac * 8;
    const uint32_t a_soff = (uint32_t)ar * (SST * 4) + ac * 16;

    // B (fp32, LDG-staged): 2048 chunks of 16B fp32 (-> 8B fp16); 4 per thread
    const float* bptr[4];
    const float* sptr[4];
    uint32_t b_soff[4];
    #pragma unroll
    for (int i = 0; i < 4; i++) {
        int ci = tid + i * NT;
        int br = ci >> 3, bc = ci & 7;
        int wr;
        if (MODE == 0) wr = nb * 128 + (br >> 1) + ((br & 1) ? ITR : 0);
        else           wr = nb * BNR + br;
        bptr[i] = W + (size_t)wr * K + bc * 4;
        sptr[i] = S + (size_t)(wr >> 7) * KB;
        b_soff[i] = (uint32_t)br * (SST * 4) + bc * 8;
    }

    float4 bv[4];
    float sc[4];
    auto LDGB = [&](int t) {
        const int k0 = t * BK, kb = k0 >> 7;
        #pragma unroll
        for (int i = 0; i < 4; i++) {
            bv[i] = *(const float4*)(bptr[i] + k0);
            sc[i] = sptr[i][kb];
        }
    };
    auto STSB = [&](int buf) {
        const uint32_t bb = sb + (uint32_t)(buf * (AST + BST) + AST) * 4;
        #pragma unroll
        for (int i = 0; i < 4; i++) {
            uint32_t u0 = pack2(bv[i].x * sc[i], bv[i].y * sc[i]);
            uint32_t u1 = pack2(bv[i].z * sc[i], bv[i].w * sc[i]);
            asm volatile("st.shared.v2.b32 [%0], {%1,%2};"
                         :: "r"(bb + b_soff[i]), "r"(u0), "r"(u1) : "memory");
        }
    };
    auto CPA = [&](int t, int buf) {
        const uint32_t ab = sb + (uint32_t)(buf * (AST + BST)) * 4;
        cp16(ab + a_soff, aptr + t * BK);
    };

    float acc[4][4][4];
    #pragma unroll
    for (int a = 0; a < 4; a++)
        #pragma unroll
        for (int b = 0; b < 4; b++)
            #pragma unroll
            for (int c = 0; c < 4; c++) acc[a][b][c] = 0.f;

    const int wm = (wid >> 3) * 64;   // warp m-offset (0/64)
    const int wn = (wid & 7) * 32;    // warp n-offset in B rows (0..224)

    auto compute = [&](int buf) {
        const uint32_t* As = (const uint32_t*)sm + buf * (AST + BST);
        const uint32_t* Bs = As + AST;
        #pragma unroll
        for (int ks = 0; ks < 2; ks++) {             // 2 k16 steps per 32-K tile
            uint32_t af[4][4], bf[4][2];
            #pragma unroll
            for (int mi = 0; mi < 4; mi++) {
                const uint32_t* p0 = As + (wm + mi * 16 + g) * SST + ks * 8 + tg;
                const uint32_t* p1 = p0 + 8 * SST;
                af[mi][0] = p0[0]; af[mi][1] = p1[0]; af[mi][2] = p0[4]; af[mi][3] = p1[4];
            }
            #pragma unroll
            for (int ni = 0; ni < 4; ni++) {
                const uint32_t* p = Bs + (wn + ni * 8 + g) * SST + ks * 8 + tg;
                bf[ni][0] = p[0]; bf[ni][1] = p[4];
            }
            #pragma unroll
            for (int mi = 0; mi < 4; mi++)
                #pragma unroll
                for (int ni = 0; ni < 4; ni++)
                    mma16(acc[mi][ni], af[mi], bf[ni]);
        }
    };

    // ---- mainloop: A double-buffered cp.async, B LDG-staged + converted ----
    CPA(0, 0);
    asm volatile("cp.async.commit_group;" ::: "memory");
    LDGB(0);
    STSB(0);
    asm volatile("cp.async.wait_group 0;" ::: "memory");
    __syncthreads();
    #pragma unroll 1
    for (int t = 0; t < KT; t++) {
        if (t + 1 < KT) {
            LDGB(t + 1);                     // long-latency loads first
            CPA(t + 1, (t + 1) & 1);
        }
        asm volatile("cp.async.commit_group;" ::: "memory");
        compute(t & 1);                      // hides the LDG latency
        if (t + 1 < KT) STSB((t + 1) & 1);
        asm volatile("cp.async.wait_group 0;" ::: "memory");
        __syncthreads();
    }

    // ---- epilogue ----
    if (MODE == 0) {
        // c0/c1 = (gate, up) of one out-col, rows g / g+8 via c2/c3
        const int ncol = nb * (BNR / 2) + (wn >> 1) + tg;   // + ni*4
        __half* D = g_dn + ((size_t)e * MPE + m0 + wm + g) * ITR + ncol;
        #pragma unroll
        for (int mi = 0; mi < 4; mi++) {
            __half* Dr0 = D + (size_t)(mi * 16) * ITR;
            __half* Dr1 = Dr0 + (size_t)8 * ITR;
            #pragma unroll
            for (int ni = 0; ni < 4; ni++) {
                float g0 = acc[mi][ni][0], u0 = acc[mi][ni][1];
                float g1 = acc[mi][ni][2], u1 = acc[mi][ni][3];
                Dr0[ni * 4] = __float2half_rn((g0 / (1.f + __expf(-g0))) * u0);
                Dr1[ni * 4] = __float2half_rn((g1 / (1.f + __expf(-g1))) * u1);
            }
        }
    } else {
        const int ncol = nb * BNR + wn + 2 * tg;            // + ni*8
        float* D = Out + ((size_t)e * MPE + m0 + wm + g) * HID + ncol;
        #pragma unroll
        for (int mi = 0; mi < 4; mi++) {
            float* Dr0 = D + (size_t)(mi * 16) * HID;
            float* Dr1 = Dr0 + (size_t)8 * HID;
            #pragma unroll
            for (int ni = 0; ni < 4; ni++) {
                float2 o0 = {acc[mi][ni][0], acc[mi][ni][1]};
                float2 o1 = {acc[mi][ni][2], acc[mi][ni][3]};
                *(float2*)(Dr0 + ni * 8) = o0;
                *(float2*)(Dr1 + ni * 8) = o1;
            }
        }
    }
}

extern "C" void kernel_launch(void* const* d_in, const int* in_sizes, int n_in,
                              void* d_out, int out_size) {
    const float* hs = (const float*)d_in[0];
    // d_in[1] = tokens_per_expert (uniform 1024/expert; matches reference reshape)
    const float* w1 = (const float*)d_in[2];
    const float* s1 = (const float*)d_in[3];
    const float* w2 = (const float*)d_in[4];
    const float* s2 = (const float*)d_in[5];
    float* out = (float*)d_out;

    cudaFuncSetAttribute(moe_gemm<0>, cudaFuncAttributeMaxDynamicSharedMemorySize, SMEM_BYTES);
    cudaFuncSetAttribute(moe_gemm<1>, cudaFuncAttributeMaxDynamicSharedMemorySize, SMEM_BYTES);

    pack_hs<<<2048, 256>>>(hs);
    // GEMM1 + silu*up: grid (2816/256, 8, 8) = (11, 8, 8)
    moe_gemm<0><<<dim3(2 * ITR / BNR, MPE / BM, E), NT, SMEM_BYTES>>>(w1, s1, nullptr);
    // GEMM2: grid (2048/256, 8, 8) = (8, 8, 8)
    moe_gemm<1><<<dim3(HID / BNR, MPE / BM, E), NT, SMEM_BYTES>>>(w2, s2, out);
}

// round 11
// speedup vs baseline: 1.0018x; 1.0018x over previous
#include <cuda_runtime.h>
#include <cuda_fp16.h>
#include <cstdint>

// Problem constants
static const int E   = 8;
static const int HID = 2048;
static const int ITR = 1408;
static const int MPE = 1024;

// GEMM tiling (fp16 operands) — R5 geometry
static const int BM  = 128;   // M rows per CTA
static const int BNR = 256;   // B-tile rows per CTA (MODE0: 128 out cols x {gate,up})
static const int BK  = 64;    // K halves per stage (= 128B row)
static const int NT  = 512;   // 16 warps
static const int SST = 36;    // smem row stride in words (32 data + 4 pad): conflict-free frags
static const int AST = BM * SST;    // 4608 words / A stage
static const int BST = BNR * SST;   // 9216 words / B stage
static const int NSTAGE = 3;
static const int SMEM_BYTES = NSTAGE * (AST + BST) * 4;  // 165888

// Packed (pre-scaled, fp16-rounded) operands + intermediate
__device__ __half g_w1[(size_t)E * 2 * ITR * HID];  // rows gate/up interleaved (packed by pack_all)
__device__ __half g_w2[(size_t)E * HID * ITR];      // packed by GEMM1 epilogue
__device__ __half g_a1[(size_t)E * MPE * HID];
__device__ __half g_dn[(size_t)E * MPE * ITR];      // silu(gate)*up, fp16

__device__ __forceinline__ uint32_t s2u(const void* p) {
    uint32_t a;
    asm("{ .reg .u64 t; cvta.to.shared.u64 t, %1; cvt.u32.u64 %0, t; }" : "=r"(a) : "l"(p));
    return a;
}
__device__ __forceinline__ void cp16(uint32_t dst, const void* src) {
    asm volatile("cp.async.cg.shared.global [%0], [%1], 16;" :: "r"(dst), "l"(src) : "memory");
}
__device__ __forceinline__ void mma16(float* c, const uint32_t* a, const uint32_t* b) {
    asm volatile(
        "mma.sync.aligned.m16n8k16.row.col.f32.f16.f16.f32 "
        "{%0,%1,%2,%3}, {%4,%5,%6,%7}, {%8,%9}, {%0,%1,%2,%3};\n"
        : "+f"(c[0]), "+f"(c[1]), "+f"(c[2]), "+f"(c[3])
        : "r"(a[0]), "r"(a[1]), "r"(a[2]), "r"(a[3]), "r"(b[0]), "r"(b[1]));
}

// ---------------- pack: hs + w1 only (w2 packed inside GEMM1) ----------------
__global__ void __launch_bounds__(256)
pack_all(const float* __restrict__ hs, const float* __restrict__ w1,
         const float* __restrict__ s1) {
    const size_t N1 = (size_t)E * 2 * ITR * (HID / 4);   // w1 float4 groups
    const size_t N3 = (size_t)E * MPE * (HID / 4);       // hs
    const size_t total = N1 + N3;
    size_t i = (size_t)blockIdx.x * blockDim.x + threadIdx.x;
    const size_t step = (size_t)gridDim.x * blockDim.x;
    for (; i < total; i += step) {
        if (i < N1) {
            const size_t f = i;
            const int kf = (int)(f % (HID / 4));
            const size_t row = f / (HID / 4);
            const int e = (int)(row / (2 * ITR));
            const int j = (int)(row % (2 * ITR));
            const int wr = (j & 1) ? (ITR + (j >> 1)) : (j >> 1);
            const float s = s1[((size_t)e * (2 * ITR / 128) + (wr >> 7)) * (HID / 128) + (kf >> 5)];
            float4 v = ((const float4*)w1)[((size_t)e * 2 * ITR + wr) * (HID / 4) + kf];
            ((__half2*)g_w1)[2 * f]     = __floats2half2_rn(v.x * s, v.y * s);
            ((__half2*)g_w1)[2 * f + 1] = __floats2half2_rn(v.z * s, v.w * s);
        } else {
            const size_t f = i - N1;
            float4 v = ((const float4*)hs)[f];
            ((__half2*)g_a1)[2 * f]     = __floats2half2_rn(v.x, v.y);
            ((__half2*)g_a1)[2 * f + 1] = __floats2half2_rn(v.z, v.w);
        }
    }
}

// ---------------- fused GEMM (fp16 mma, fp32 accumulate) ----------------
// MODE 0: gate_up (K=2048) + silu*up -> g_dn; also packs w2 -> g_w2 in epilogue.
// MODE 1: down    (K=1408) -> Out (fp32).
template <int MODE>
__global__ void __launch_bounds__(NT, 1)
moe_gemm(const float* __restrict__ w2, const float* __restrict__ s2,
         float* __restrict__ Out) {
    constexpr int K  = (MODE == 0) ? HID : ITR;          // in halves
    constexpr int KT = K / BK;                           // 32 / 22
    constexpr int NWROWS = (MODE == 0) ? 2 * ITR : HID;

    extern __shared__ float sm[];
    const uint32_t sb = s2u(sm);
    const int tid = threadIdx.x, wid = tid >> 5, lane = tid & 31;
    const int g = lane >> 2, tg = lane & 3;
    const int e = blockIdx.z, m0 = blockIdx.y * BM, nb = blockIdx.x;

    const __half* Ag = ((MODE == 0) ? g_a1 : g_dn) + ((size_t)e * MPE + m0) * K;
    const __half* Bg = ((MODE == 0) ? g_w1 : g_w2) + ((size_t)e * NWROWS + (size_t)nb * BNR) * K;

    // cp.async: 16B chunks (8 halves); 8 chunks per 64-half row
    auto issue = [&](int t, int buf) {
        const int k0 = t * BK;
        const uint32_t abase = sb + (uint32_t)(buf * (AST + BST)) * 4;
        const uint32_t bbase = abase + (uint32_t)AST * 4;
        #pragma unroll
        for (int i = 0; i < 2; i++) {                // A: 1024 chunks
            int ci = tid + i * NT;
            int r = ci >> 3, c = ci & 7;
            cp16(abase + (uint32_t)r * (SST * 4) + c * 16, Ag + (size_t)r * K + k0 + c * 8);
        }
        #pragma unroll
        for (int i = 0; i < 4; i++) {                // B: 2048 chunks
            int ci = tid + i * NT;
            int r = ci >> 3, c = ci & 7;
            cp16(bbase + (uint32_t)r * (SST * 4) + c * 16, Bg + (size_t)r * K + k0 + c * 8);
        }
    };

    float acc[4][4][4];
    #pragma unroll
    for (int a = 0; a < 4; a++)
        #pragma unroll
        for (int b = 0; b < 4; b++)
            #pragma unroll
            for (int c = 0; c < 4; c++) acc[a][b][c] = 0.f;

    const int wm = (wid >> 3) * 64;   // warp m-offset (0/64)
    const int wn = (wid & 7) * 32;    // warp n-offset in B rows (0..224)

    auto compute = [&](int buf) {
        const uint32_t* As = (const uint32_t*)sm + buf * (AST + BST);
        const uint32_t* Bs = As + AST;
        #pragma unroll
        for (int ks = 0; ks < 4; ks++) {             // k16 steps (8 words each)
            uint32_t af[4][4], bf[4][2];
            #pragma unroll
            for (int mi = 0; mi < 4; mi++) {
                const uint32_t* p0 = As + (wm + mi * 16 + g) * SST + ks * 8 + tg;
                const uint32_t* p1 = p0 + 8 * SST;
                af[mi][0] = p0[0]; af[mi][1] = p1[0]; af[mi][2] = p0[4]; af[mi][3] = p1[4];
            }
            #pragma unroll
            for (int ni = 0; ni < 4; ni++) {
                const uint32_t* p = Bs + (wn + ni * 8 + g) * SST + ks * 8 + tg;
                bf[ni][0] = p[0]; bf[ni][1] = p[4];
            }
            #pragma unroll
            for (int mi = 0; mi < 4; mi++)
                #pragma unroll
                for (int ni = 0; ni < 4; ni++)
                    mma16(acc[mi][ni], af[mi], bf[ni]);
        }
    };

    // ---- 3-stage pipeline: one tile always in flight during compute ----
    issue(0, 0);
    asm volatile("cp.async.commit_group;" ::: "memory");
    issue(1, 1);
    asm volatile("cp.async.commit_group;" ::: "memory");
    int bufc = 0, bufn = 2;
    #pragma unroll 1
    for (int t = 0; t < KT; t++) {
        asm volatile("cp.async.wait_group 1;" ::: "memory");
        __syncthreads();
        if (t + 2 < KT) issue(t + 2, bufn);
        asm volatile("cp.async.commit_group;" ::: "memory");
        compute(bufc);
        bufc = (bufc == 2) ? 0 : bufc + 1;
        bufn = (bufn == 2) ? 0 : bufn + 1;
    }

    // ---- epilogue ----
    if (MODE == 0) {
        // c0/c1 = (gate, up) of one out-col, rows g / g+8 via c2/c3
        const int ncol = nb * (BNR / 2) + (wn >> 1) + tg;   // + ni*4
        __half* D = g_dn + ((size_t)e * MPE + m0 + wm + g) * ITR + ncol;
        #pragma unroll
        for (int mi = 0; mi < 4; mi++) {
            __half* Dr0 = D + (size_t)(mi * 16) * ITR;
            __half* Dr1 = Dr0 + (size_t)8 * ITR;
            #pragma unroll
            for (int ni = 0; ni < 4; ni++) {
                float g0 = acc[mi][ni][0], u0 = acc[mi][ni][1];
                float g1 = acc[mi][ni][2], u1 = acc[mi][ni][3];
                Dr0[ni * 4] = __float2half_rn((g0 / (1.f + __expf(-g0))) * u0);
                Dr1[ni * 4] = __float2half_rn((g1 / (1.f + __expf(-g1))) * u1);
            }
        }
        // ---- pack w2 -> g_w2 (spread across all 704 CTAs; 16 float4/thread) ----
        const size_t NTH = (size_t)11 * 8 * 8 * NT;   // total threads = 360448
        size_t f = (size_t)(((size_t)blockIdx.z * gridDim.y + blockIdx.y) * gridDim.x
                            + blockIdx.x) * NT + tid;
        #pragma unroll 1
        for (int i = 0; i < 16; i++, f += NTH) {
            const int kf = (int)(f % (ITR / 4));
            const size_t row = f / (ITR / 4);
            const int e2 = (int)(row >> 11);          // row / HID
            const int n  = (int)(row & 2047);         // row % HID
            const float s = s2[((size_t)e2 * (HID / 128) + (n >> 7)) * (ITR / 128) + (kf >> 5)];
            float4 v = ((const float4*)w2)[f];
            ((__half2*)g_w2)[2 * f]     = __floats2half2_rn(v.x * s, v.y * s);
            ((__half2*)g_w2)[2 * f + 1] = __floats2half2_rn(v.z * s, v.w * s);
        }
    } else {
        const int ncol = nb * BNR + wn + 2 * tg;            // + ni*8
        float* D = Out + ((size_t)e * MPE + m0 + wm + g) * HID + ncol;
        #pragma unroll
        for (int mi = 0; mi < 4; mi++) {
            float* Dr0 = D + (size_t)(mi * 16) * HID;
            float* Dr1 = Dr0 + (size_t)8 * HID;
            #pragma unroll
            for (int ni = 0; ni < 4; ni++) {
                float2 o0 = {acc[mi][ni][0], acc[mi][ni][1]};
                float2 o1 = {acc[mi][ni][2], acc[mi][ni][3]};
                *(float2*)(Dr0 + ni * 8) = o0;
                *(float2*)(Dr1 + ni * 8) = o1;
            }
        }
    }
}

extern "C" void kernel_launch(void* const* d_in, const int* in_sizes, int n_in,
                              void* d_out, int out_size) {
    const float* hs = (const float*)d_in[0];
    // d_in[1] = tokens_per_expert (uniform 1024/expert; matches reference reshape)
    const float* w1 = (const float*)d_in[2];
    const float* s1 = (const float*)d_in[3];
    const float* w2 = (const float*)d_in[4];
    const float* s2 = (const float*)d_in[5];
    float* out = (float*)d_out;

    cudaFuncSetAttribute(moe_gemm<0>, cudaFuncAttributeMaxDynamicSharedMemorySize, SMEM_BYTES);
    cudaFuncSetAttribute(moe_gemm<1>, cudaFuncAttributeMaxDynamicSharedMemorySize, SMEM_BYTES);

    pack_all<<<4096, 256>>>(hs, w1, s1);
    // GEMM1 + silu*up (+ w2 pack): grid (2816/256, 8, 8) = (11, 8, 8)
    moe_gemm<0><<<dim3(2 * ITR / BNR, MPE / BM, E), NT, SMEM_BYTES>>>(w2, s2, nullptr);
    // GEMM2: grid (2048/256, 8, 8) = (8, 8, 8)
    moe_gemm<1><<<dim3(HID / BNR, MPE / BM, E), NT, SMEM_BYTES>>>(nullptr, nullptr, out);
}

// round 12
// speedup vs baseline: 1.0254x; 1.0236x over previous
#include <cuda_runtime.h>
#include <cuda_fp16.h>
#include <cstdint>

// Problem constants
static const int E   = 8;
static const int HID = 2048;
static const int ITR = 1408;
static const int MPE = 1024;

// GEMM tiling (fp16 operands) — R5 geometry
static const int BM  = 128;   // M rows per CTA
static const int BNR = 256;   // B-tile rows per CTA (MODE0: 128 out cols x {gate,up})
static const int BK  = 64;    // K halves per stage (= 128B row)
static const int NT  = 512;   // 16 warps
static const int SST = 36;    // smem row stride in words (32 data + 4 pad): conflict-free frags
static const int AST = BM * SST;    // 4608 words / A stage
static const int BST = BNR * SST;   // 9216 words / B stage
static const int SMEM_BYTES = 2 * (AST + BST) * 4;  // 110592

// Packed (pre-scaled, fp16-rounded) operands + intermediate
__device__ __half g_w1[(size_t)E * 2 * ITR * HID];  // rows gate/up interleaved (pack_all)
__device__ __half g_w2[(size_t)E * HID * ITR];      // packed by GEMM1 epilogue
__device__ __half g_a1[(size_t)E * MPE * HID];
__device__ __half g_dn[(size_t)E * MPE * ITR];      // silu(gate)*up, fp16

__device__ __forceinline__ uint32_t s2u(const void* p) {
    uint32_t a;
    asm("{ .reg .u64 t; cvta.to.shared.u64 t, %1; cvt.u32.u64 %0, t; }" : "=r"(a) : "l"(p));
    return a;
}
__device__ __forceinline__ void cp16(uint32_t dst, const void* src) {
    asm volatile("cp.async.cg.shared.global [%0], [%1], 16;" :: "r"(dst), "l"(src) : "memory");
}
__device__ __forceinline__ void mma16(float* c, const uint32_t* a, const uint32_t* b) {
    asm volatile(
        "mma.sync.aligned.m16n8k16.row.col.f32.f16.f16.f32 "
        "{%0,%1,%2,%3}, {%4,%5,%6,%7}, {%8,%9}, {%0,%1,%2,%3};\n"
        : "+f"(c[0]), "+f"(c[1]), "+f"(c[2]), "+f"(c[3])
        : "r"(a[0]), "r"(a[1]), "r"(a[2]), "r"(a[3]), "r"(b[0]), "r"(b[1]));
}

// ---------------- pack: hs + w1 only (w2 packed inside GEMM1) ----------------
__global__ void __launch_bounds__(256)
pack_all(const float* __restrict__ hs, const float* __restrict__ w1,
         const float* __restrict__ s1) {
    const size_t N1 = (size_t)E * 2 * ITR * (HID / 4);   // w1 float4 groups
    const size_t N3 = (size_t)E * MPE * (HID / 4);       // hs
    const size_t total = N1 + N3;
    size_t i = (size_t)blockIdx.x * blockDim.x + threadIdx.x;
    const size_t step = (size_t)gridDim.x * blockDim.x;
    for (; i < total; i += step) {
        if (i < N1) {
            const size_t f = i;
            const int kf = (int)(f % (HID / 4));
            const size_t row = f / (HID / 4);
            const int e = (int)(row / (2 * ITR));
            const int j = (int)(row % (2 * ITR));
            const int wr = (j & 1) ? (ITR + (j >> 1)) : (j >> 1);
            const float s = s1[((size_t)e * (2 * ITR / 128) + (wr >> 7)) * (HID / 128) + (kf >> 5)];
            float4 v = ((const float4*)w1)[((size_t)e * 2 * ITR + wr) * (HID / 4) + kf];
            ((__half2*)g_w1)[2 * f]     = __floats2half2_rn(v.x * s, v.y * s);
            ((__half2*)g_w1)[2 * f + 1] = __floats2half2_rn(v.z * s, v.w * s);
        } else {
            const size_t f = i - N1;
            float4 v = ((const float4*)hs)[f];
            ((__half2*)g_a1)[2 * f]     = __floats2half2_rn(v.x, v.y);
            ((__half2*)g_a1)[2 * f + 1] = __floats2half2_rn(v.z, v.w);
        }
    }
}

// ---------------- fused GEMM (fp16 mma, fp32 accumulate) — R5 pipeline ------
// MODE 0: gate_up (K=2048) + silu*up -> g_dn; also packs w2 -> g_w2 in epilogue.
// MODE 1: down    (K=1408) -> Out (fp32).
template <int MODE>
__global__ void __launch_bounds__(NT, 1)
moe_gemm(const float* __restrict__ w2, const float* __restrict__ s2,
         float* __restrict__ Out) {
    constexpr int K  = (MODE == 0) ? HID : ITR;          // in halves
    constexpr int KT = K / BK;                           // 32 / 22
    constexpr int NWROWS = (MODE == 0) ? 2 * ITR : HID;

    extern __shared__ float sm[];
    const uint32_t sb = s2u(sm);
    const int tid = threadIdx.x, wid = tid >> 5, lane = tid & 31;
    const int g = lane >> 2, tg = lane & 3;
    const int e = blockIdx.z, m0 = blockIdx.y * BM, nb = blockIdx.x;

    const __half* Ag = ((MODE == 0) ? g_a1 : g_dn) + ((size_t)e * MPE + m0) * K;
    const __half* Bg = ((MODE == 0) ? g_w1 : g_w2) + ((size_t)e * NWROWS + (size_t)nb * BNR) * K;

    // cp.async: 16B chunks (8 halves); 8 chunks per 64-half row
    auto issue = [&](int t) {
        const int buf = t & 1;
        const int k0 = t * BK;
        const uint32_t abase = sb + (uint32_t)(buf * AST) * 4;
        const uint32_t bbase = sb + (uint32_t)(2 * AST + buf * BST) * 4;
        #pragma unroll
        for (int i = 0; i < 2; i++) {                // A: 1024 chunks
            int ci = tid + i * NT;
            int r = ci >> 3, c = ci & 7;
            cp16(abase + (uint32_t)r * (SST * 4) + c * 16, Ag + (size_t)r * K + k0 + c * 8);
        }
        #pragma unroll
        for (int i = 0; i < 4; i++) {                // B: 2048 chunks
            int ci = tid + i * NT;
            int r = ci >> 3, c = ci & 7;
            cp16(bbase + (uint32_t)r * (SST * 4) + c * 16, Bg + (size_t)r * K + k0 + c * 8);
        }
    };

    float acc[4][4][4];
    #pragma unroll
    for (int a = 0; a < 4; a++)
        #pragma unroll
        for (int b = 0; b < 4; b++)
            #pragma unroll
            for (int c = 0; c < 4; c++) acc[a][b][c] = 0.f;

    const int wm = (wid >> 3) * 64;   // warp m-offset (0/64)
    const int wn = (wid & 7) * 32;    // warp n-offset in B rows (0..224)

    auto compute = [&](int buf) {
        const uint32_t* As = (const uint32_t*)sm + buf * AST;
        const uint32_t* Bs = (const uint32_t*)sm + 2 * AST + buf * BST;
        #pragma unroll
        for (int ks = 0; ks < 4; ks++) {             // k16 steps (8 words each)
            uint32_t af[4][4], bf[4][2];
            #pragma unroll
            for (int mi = 0; mi < 4; mi++) {
                const uint32_t* p0 = As + (wm + mi * 16 + g) * SST + ks * 8 + tg;
                const uint32_t* p1 = p0 + 8 * SST;
                af[mi][0] = p0[0]; af[mi][1] = p1[0]; af[mi][2] = p0[4]; af[mi][3] = p1[4];
            }
            #pragma unroll
            for (int ni = 0; ni < 4; ni++) {
                const uint32_t* p = Bs + (wn + ni * 8 + g) * SST + ks * 8 + tg;
                bf[ni][0] = p[0]; bf[ni][1] = p[4];
            }
            #pragma unroll
            for (int mi = 0; mi < 4; mi++)
                #pragma unroll
                for (int ni = 0; ni < 4; ni++)
                    mma16(acc[mi][ni], af[mi], bf[ni]);
        }
    };

    // ---- 2-stage pipeline (R5) ----
    issue(0);
    asm volatile("cp.async.commit_group;" ::: "memory");
    for (int t = 0; t < KT; t++) {
        asm volatile("cp.async.wait_group 0;" ::: "memory");
        __syncthreads();
        if (t + 1 < KT) {
            issue(t + 1);
            asm volatile("cp.async.commit_group;" ::: "memory");
        }
        compute(t & 1);
    }

    // ---- epilogue ----
    if (MODE == 0) {
        // c0/c1 = (gate, up) of one out-col, rows g / g+8 via c2/c3
        const int ncol = nb * (BNR / 2) + (wn >> 1) + tg;   // + ni*4
        __half* D = g_dn + ((size_t)e * MPE + m0 + wm + g) * ITR + ncol;
        #pragma unroll
        for (int mi = 0; mi < 4; mi++) {
            __half* Dr0 = D + (size_t)(mi * 16) * ITR;
            __half* Dr1 = Dr0 + (size_t)8 * ITR;
            #pragma unroll
            for (int ni = 0; ni < 4; ni++) {
                float g0 = acc[mi][ni][0], u0 = acc[mi][ni][1];
                float g1 = acc[mi][ni][2], u1 = acc[mi][ni][3];
                Dr0[ni * 4] = __float2half_rn((g0 / (1.f + __expf(-g0))) * u0);
                Dr1[ni * 4] = __float2half_rn((g1 / (1.f + __expf(-g1))) * u1);
            }
        }
        // ---- pack w2 -> g_w2 (spread across all 704 CTAs; 16 float4/thread) ----
        const size_t NTH = (size_t)11 * 8 * 8 * NT;   // total threads = 360448
        size_t f = (size_t)(((size_t)blockIdx.z * gridDim.y + blockIdx.y) * gridDim.x
                            + blockIdx.x) * NT + tid;
        #pragma unroll 1
        for (int i = 0; i < 16; i++, f += NTH) {
            const int kf = (int)(f % (ITR / 4));
            const size_t row = f / (ITR / 4);
            const int e2 = (int)(row >> 11);          // row / HID
            const int n  = (int)(row & 2047);         // row % HID
            const float s = s2[((size_t)e2 * (HID / 128) + (n >> 7)) * (ITR / 128) + (kf >> 5)];
            float4 v = ((const float4*)w2)[f];
            ((__half2*)g_w2)[2 * f]     = __floats2half2_rn(v.x * s, v.y * s);
            ((__half2*)g_w2)[2 * f + 1] = __floats2half2_rn(v.z * s, v.w * s);
        }
    } else {
        const int ncol = nb * BNR + wn + 2 * tg;            // + ni*8
        float* D = Out + ((size_t)e * MPE + m0 + wm + g) * HID + ncol;
        #pragma unroll
        for (int mi = 0; mi < 4; mi++) {
            float* Dr0 = D + (size_t)(mi * 16) * HID;
            float* Dr1 = Dr0 + (size_t)8 * HID;
            #pragma unroll
            for (int ni = 0; ni < 4; ni++) {
                float2 o0 = {acc[mi][ni][0], acc[mi][ni][1]};
                float2 o1 = {acc[mi][ni][2], acc[mi][ni][3]};
                *(float2*)(Dr0 + ni * 8) = o0;
                *(float2*)(Dr1 + ni * 8) = o1;
            }
        }
    }
}

extern "C" void kernel_launch(void* const* d_in, const int* in_sizes, int n_in,
                              void* d_out, int out_size) {
    const float* hs = (const float*)d_in[0];
    // d_in[1] = tokens_per_expert (uniform 1024/expert; matches reference reshape)
    const float* w1 = (const float*)d_in[2];
    const float* s1 = (const float*)d_in[3];
    const float* w2 = (const float*)d_in[4];
    const float* s2 = (const float*)d_in[5];
    float* out = (float*)d_out;

    cudaFuncSetAttribute(moe_gemm<0>, cudaFuncAttributeMaxDynamicSharedMemorySize, SMEM_BYTES);
    cudaFuncSetAttribute(moe_gemm<1>, cudaFuncAttributeMaxDynamicSharedMemorySize, SMEM_BYTES);

    pack_all<<<4096, 256>>>(hs, w1, s1);
    // GEMM1 + silu*up (+ w2 pack): grid (2816/256, 8, 8) = (11, 8, 8)
    moe_gemm<0><<<dim3(2 * ITR / BNR, MPE / BM, E), NT, SMEM_BYTES>>>(w2, s2, nullptr);
    // GEMM2: grid (2048/256, 8, 8) = (8, 8, 8)
    moe_gemm<1><<<dim3(HID / BNR, MPE / BM, E), NT, SMEM_BYTES>>>(nullptr, nullptr, out);
}

// round 13
// speedup vs baseline: 1.0283x; 1.0028x over previous
#include <cuda_runtime.h>
#include <cuda_fp16.h>
#include <cstdint>

// Problem constants
static const int E   = 8;
static const int HID = 2048;
static const int ITR = 1408;
static const int MPE = 1024;

// GEMM tiling (fp16 operands) — R5 core
static const int BNR = 256;   // B-tile rows per CTA
static const int BK  = 64;    // K halves per stage (= 128B row)
static const int NT  = 512;   // 16 warps
static const int SST = 36;    // smem row stride in words: conflict-free frags
static const int BST = BNR * SST;

// Packed (pre-scaled, fp16-rounded) operands + intermediate
__device__ __half g_w1[(size_t)E * 2 * ITR * HID];  // NATURAL order [e][2*ITR][HID]
__device__ __half g_w2[(size_t)E * HID * ITR];
__device__ __half g_a1[(size_t)E * MPE * HID];
__device__ __half g_dn[(size_t)E * MPE * ITR];      // silu(gate)*up, fp16

__device__ __forceinline__ uint32_t s2u(const void* p) {
    uint32_t a;
    asm("{ .reg .u64 t; cvta.to.shared.u64 t, %1; cvt.u32.u64 %0, t; }" : "=r"(a) : "l"(p));
    return a;
}
__device__ __forceinline__ void cp16(uint32_t dst, const void* src) {
    asm volatile("cp.async.cg.shared.global [%0], [%1], 16;" :: "r"(dst), "l"(src) : "memory");
}
__device__ __forceinline__ void mma16(float* c, const uint32_t* a, const uint32_t* b) {
    asm volatile(
        "mma.sync.aligned.m16n8k16.row.col.f32.f16.f16.f32 "
        "{%0,%1,%2,%3}, {%4,%5,%6,%7}, {%8,%9}, {%0,%1,%2,%3};\n"
        : "+f"(c[0]), "+f"(c[1]), "+f"(c[2]), "+f"(c[3])
        : "r"(a[0]), "r"(a[1]), "r"(a[2]), "r"(a[3]), "r"(b[0]), "r"(b[1]));
}

// ---------------- pack: 3 branch-free sections (w1 natural, w2, hs) ----------
__global__ void __launch_bounds__(256)
pack_all(const float* __restrict__ hs, const float* __restrict__ w1,
         const float* __restrict__ s1, const float* __restrict__ w2,
         const float* __restrict__ s2) {
    const size_t step = (size_t)gridDim.x * blockDim.x;
    size_t f = (size_t)blockIdx.x * blockDim.x + threadIdx.x;
    if (blockIdx.y == 0) {
        // w1 natural: row = f>>9 (512 float4/row), k4 = f&511; scale idx all-shift
        const size_t N1 = (size_t)E * 2 * ITR * (HID / 4);
        for (; f < N1; f += step) {
            const float s = s1[((f >> 16) << 4) | ((f >> 5) & 15)];
            float4 v = ((const float4*)w1)[f];
            ((__half2*)g_w1)[2 * f]     = __floats2half2_rn(v.x * s, v.y * s);
            ((__half2*)g_w1)[2 * f + 1] = __floats2half2_rn(v.z * s, v.w * s);
        }
    } else if (blockIdx.y == 1) {
        const size_t N2 = (size_t)E * HID * (ITR / 4);
        for (; f < N2; f += step) {
            const uint32_t kf = (uint32_t)(f % (ITR / 4));
            const uint32_t row = (uint32_t)(f / (ITR / 4));
            const float s = s2[(size_t)(row >> 7) * (ITR / 128) + (kf >> 5)];
            float4 v = ((const float4*)w2)[f];
            ((__half2*)g_w2)[2 * f]     = __floats2half2_rn(v.x * s, v.y * s);
            ((__half2*)g_w2)[2 * f + 1] = __floats2half2_rn(v.z * s, v.w * s);
        }
    } else {
        const size_t N3 = (size_t)E * MPE * (HID / 4);
        for (; f < N3; f += step) {
            float4 v = ((const float4*)hs)[f];
            ((__half2*)g_a1)[2 * f]     = __floats2half2_rn(v.x, v.y);
            ((__half2*)g_a1)[2 * f + 1] = __floats2half2_rn(v.z, v.w);
        }
    }
}

// ---------------- fused GEMM (fp16 mma, fp32 accumulate) — R5 pipeline ------
// MODE 0: gate_up (K=2048, BM=128) + silu*up -> g_dn; B rows interleaved via
//         per-thread pointer map (g_w1 is natural order).
// MODE 1: down (K=1408, BM=64) -> Out (fp32); 1024 CTAs kill the wave tail.
template <int MODE>
__global__ void __launch_bounds__(NT, 1)
moe_gemm(float* __restrict__ Out) {
    constexpr int K   = (MODE == 0) ? HID : ITR;
    constexpr int KT  = K / BK;                     // 32 / 22
    constexpr int BMk = (MODE == 0) ? 128 : 64;
    constexpr int MI  = (MODE == 0) ? 4 : 2;        // m-frags per warp
    constexpr int AI  = BMk * 8 / NT;               // A cp16 per thread (2 / 1)
    constexpr int AST_ = BMk * SST;

    extern __shared__ float sm[];
    const uint32_t sb = s2u(sm);
    const int tid = threadIdx.x, wid = tid >> 5, lane = tid & 31;
    const int g = lane >> 2, tg = lane & 3;
    const int e = blockIdx.z, m0 = blockIdx.y * BMk, nb = blockIdx.x;

    const __half* Ag = ((MODE == 0) ? g_a1 : g_dn) + ((size_t)e * MPE + m0) * K;

    // Per-thread B global pointers (prologue-only): MODE0 applies gate/up interleave.
    const __half* wp[4];
    #pragma unroll
    for (int i = 0; i < 4; i++) {
        int ci = tid + i * NT;
        int br = ci >> 3, c = ci & 7;
        int wr;
        const __half* Wb;
        if (MODE == 0) {
            wr = nb * 128 + (br >> 1) + ((br & 1) ? ITR : 0);
            Wb = g_w1 + (size_t)e * 2 * ITR * K;
        } else {
            wr = nb * BNR + br;
            Wb = g_w2 + (size_t)e * HID * K;
        }
        wp[i] = Wb + (size_t)wr * K + c * 8;
    }

    auto issue = [&](int t) {
        const int buf = t & 1;
        const int k0 = t * BK;
        const uint32_t abase = sb + (uint32_t)(buf * AST_) * 4;
        const uint32_t bbase = sb + (uint32_t)(2 * AST_ + buf * BST) * 4;
        #pragma unroll
        for (int i = 0; i < AI; i++) {
            int ci = tid + i * NT;
            int r = ci >> 3, c = ci & 7;
            cp16(abase + (uint32_t)r * (SST * 4) + c * 16, Ag + (size_t)r * K + k0 + c * 8);
        }
        #pragma unroll
        for (int i = 0; i < 4; i++) {
            int ci = tid + i * NT;
            int r = ci >> 3, c = ci & 7;
            cp16(bbase + (uint32_t)r * (SST * 4) + c * 16, wp[i] + k0);
        }
    };

    float acc[MI][4][4];
    #pragma unroll
    for (int a = 0; a < MI; a++)
        #pragma unroll
        for (int b = 0; b < 4; b++)
            #pragma unroll
            for (int c = 0; c < 4; c++) acc[a][b][c] = 0.f;

    const int wm = (wid >> 3) * (BMk / 2);   // warp m-offset
    const int wn = (wid & 7) * 32;           // warp n-offset in B rows

    auto compute = [&](int buf) {
        const uint32_t* As = (const uint32_t*)sm + buf * AST_;
        const uint32_t* Bs = (const uint32_t*)sm + 2 * AST_ + buf * BST;
        #pragma unroll
        for (int ks = 0; ks < 4; ks++) {
            uint32_t af[MI][4], bf[4][2];
            #pragma unroll
            for (int mi = 0; mi < MI; mi++) {
                const uint32_t* p0 = As + (wm + mi * 16 + g) * SST + ks * 8 + tg;
                const uint32_t* p1 = p0 + 8 * SST;
                af[mi][0] = p0[0]; af[mi][1] = p1[0]; af[mi][2] = p0[4]; af[mi][3] = p1[4];
            }
            #pragma unroll
            for (int ni = 0; ni < 4; ni++) {
                const uint32_t* p = Bs + (wn + ni * 8 + g) * SST + ks * 8 + tg;
                bf[ni][0] = p[0]; bf[ni][1] = p[4];
            }
            #pragma unroll
            for (int mi = 0; mi < MI; mi++)
                #pragma unroll
                for (int ni = 0; ni < 4; ni++)
                    mma16(acc[mi][ni], af[mi], bf[ni]);
        }
    };

    // ---- 2-stage pipeline (R5) ----
    issue(0);
    asm volatile("cp.async.commit_group;" ::: "memory");
    for (int t = 0; t < KT; t++) {
        asm volatile("cp.async.wait_group 0;" ::: "memory");
        __syncthreads();
        if (t + 1 < KT) {
            issue(t + 1);
            asm volatile("cp.async.commit_group;" ::: "memory");
        }
        compute(t & 1);
    }

    // ---- epilogue ----
    if (MODE == 0) {
        const int ncol = nb * (BNR / 2) + (wn >> 1) + tg;   // + ni*4
        __half* D = g_dn + ((size_t)e * MPE + m0 + wm + g) * ITR + ncol;
        #pragma unroll
        for (int mi = 0; mi < MI; mi++) {
            __half* Dr0 = D + (size_t)(mi * 16) * ITR;
            __half* Dr1 = Dr0 + (size_t)8 * ITR;
            #pragma unroll
            for (int ni = 0; ni < 4; ni++) {
                float g0 = acc[mi][ni][0], u0 = acc[mi][ni][1];
                float g1 = acc[mi][ni][2], u1 = acc[mi][ni][3];
                Dr0[ni * 4] = __float2half_rn((g0 / (1.f + __expf(-g0))) * u0);
                Dr1[ni * 4] = __float2half_rn((g1 / (1.f + __expf(-g1))) * u1);
            }
        }
    } else {
        const int ncol = nb * BNR + wn + 2 * tg;            // + ni*8
        float* D = Out + ((size_t)e * MPE + m0 + wm + g) * HID + ncol;
        #pragma unroll
        for (int mi = 0; mi < MI; mi++) {
            float* Dr0 = D + (size_t)(mi * 16) * HID;
            float* Dr1 = Dr0 + (size_t)8 * HID;
            #pragma unroll
            for (int ni = 0; ni < 4; ni++) {
                float2 o0 = {acc[mi][ni][0], acc[mi][ni][1]};
                float2 o1 = {acc[mi][ni][2], acc[mi][ni][3]};
                *(float2*)(Dr0 + ni * 8) = o0;
                *(float2*)(Dr1 + ni * 8) = o1;
            }
        }
    }
}

extern "C" void kernel_launch(void* const* d_in, const int* in_sizes, int n_in,
                              void* d_out, int out_size) {
    const float* hs = (const float*)d_in[0];
    // d_in[1] = tokens_per_expert (uniform 1024/expert; matches reference reshape)
    const float* w1 = (const float*)d_in[2];
    const float* s1 = (const float*)d_in[3];
    const float* w2 = (const float*)d_in[4];
    const float* s2 = (const float*)d_in[5];
    float* out = (float*)d_out;

    const int SM0 = 2 * (128 * SST + BST) * 4;  // 110592
    const int SM1 = 2 * (64 * SST + BST) * 4;   //  92160
    cudaFuncSetAttribute(moe_gemm<0>, cudaFuncAttributeMaxDynamicSharedMemorySize, SM0);
    cudaFuncSetAttribute(moe_gemm<1>, cudaFuncAttributeMaxDynamicSharedMemorySize, SM1);

    pack_all<<<dim3(1536, 3), 256>>>(hs, w1, s1, w2, s2);
    // GEMM1 + silu*up: grid (11, 8, 8) = 704 CTAs
    moe_gemm<0><<<dim3(2 * ITR / BNR, MPE / 128, E), NT, SM0>>>(nullptr);
    // GEMM2: grid (8, 16, 8) = 1024 CTAs (BM=64 -> 98.8% last-wave efficiency)
    moe_gemm<1><<<dim3(HID / BNR, MPE / 64, E), NT, SM1>>>(out);
}

// round 16
// speedup vs baseline: 1.0791x; 1.0494x over previous
#include <cuda_runtime.h>
#include <cuda_fp16.h>
#include <cstdint>

// Problem constants
static const int E   = 8;
static const int HID = 2048;
static const int ITR = 1408;
static const int MPE = 1024;

// GEMM tiling (fp16 operands) — R5 geometry, both modes
static const int BM  = 128;   // M rows per CTA
static const int BNR = 256;   // B-tile rows per CTA (MODE0: 128 out cols x {gate,up})
static const int BK  = 64;    // K halves per stage (= 128B row)
static const int NT  = 512;   // 16 warps
static const int SST = 36;    // smem row stride in words (32 data + 4 pad): conflict-free frags
static const int AST = BM * SST;    // 4608 words / A stage
static const int BST = BNR * SST;   // 9216 words / B stage
static const int SMEM_BYTES = 2 * (AST + BST) * 4;  // 110592

// Packed (pre-scaled, fp16-rounded) operands + intermediate
__device__ __half g_w1[(size_t)E * 2 * ITR * HID];  // rows gate/up INTERLEAVED
__device__ __half g_w2[(size_t)E * HID * ITR];
__device__ __half g_a1[(size_t)E * MPE * HID];
__device__ __half g_dn[(size_t)E * MPE * ITR];      // silu(gate)*up, fp16

__device__ __forceinline__ uint32_t s2u(const void* p) {
    uint32_t a;
    asm("{ .reg .u64 t; cvta.to.shared.u64 t, %1; cvt.u32.u64 %0, t; }" : "=r"(a) : "l"(p));
    return a;
}
__device__ __forceinline__ void cp16(uint32_t dst, const void* src) {
    asm volatile("cp.async.cg.shared.global [%0], [%1], 16;" :: "r"(dst), "l"(src) : "memory");
}
__device__ __forceinline__ void mma16(float* c, const uint32_t* a, const uint32_t* b) {
    asm volatile(
        "mma.sync.aligned.m16n8k16.row.col.f32.f16.f16.f32 "
        "{%0,%1,%2,%3}, {%4,%5,%6,%7}, {%8,%9}, {%0,%1,%2,%3};\n"
        : "+f"(c[0]), "+f"(c[1]), "+f"(c[2]), "+f"(c[3])
        : "r"(a[0]), "r"(a[1]), "r"(a[2]), "r"(a[3]), "r"(b[0]), "r"(b[1]));
}

// ------- pack: 3 branch-free grid sections (w1 interleaved-dst, w2, hs) ------
__global__ void __launch_bounds__(256)
pack_all(const float* __restrict__ hs, const float* __restrict__ w1,
         const float* __restrict__ s1, const float* __restrict__ w2,
         const float* __restrict__ s2) {
    const size_t step = (size_t)gridDim.x * blockDim.x;
    size_t f = (size_t)blockIdx.x * blockDim.x + threadIdx.x;
    if (blockIdx.y == 0) {
        // dst f is in interleaved layout: dst row j = f>>9 (512 float4/row)
        const size_t N1 = (size_t)E * 2 * ITR * (HID / 4);
        for (; f < N1; f += step) {
            const uint32_t j  = (uint32_t)(f >> 9);
            const uint32_t e  = j / (2 * ITR);          // const-div -> mul/shift
            const uint32_t jl = j - e * (2 * ITR);
            const uint32_t wr = (jl >> 1) + ((jl & 1) ? ITR : 0);
            const uint32_t srow = e * (2 * ITR) + wr;   // natural source row
            const size_t   src  = ((size_t)srow << 9) | (f & 511);
            const float s = s1[((size_t)(srow >> 7) << 4) | ((f >> 5) & 15)];
            float4 v = ((const float4*)w1)[src];
            ((__half2*)g_w1)[2 * f]     = __floats2half2_rn(v.x * s, v.y * s);
            ((__half2*)g_w1)[2 * f + 1] = __floats2half2_rn(v.z * s, v.w * s);
        }
    } else if (blockIdx.y == 1) {
        const size_t N2 = (size_t)E * HID * (ITR / 4);
        for (; f < N2; f += step) {
            const uint32_t kf  = (uint32_t)(f % (ITR / 4));
            const uint32_t row = (uint32_t)(f / (ITR / 4));
            const float s = s2[(size_t)(row >> 7) * (ITR / 128) + (kf >> 5)];
            float4 v = ((const float4*)w2)[f];
            ((__half2*)g_w2)[2 * f]     = __floats2half2_rn(v.x * s, v.y * s);
            ((__half2*)g_w2)[2 * f + 1] = __floats2half2_rn(v.z * s, v.w * s);
        }
    } else {
        const size_t N3 = (size_t)E * MPE * (HID / 4);
        for (; f < N3; f += step) {
            float4 v = ((const float4*)hs)[f];
            ((__half2*)g_a1)[2 * f]     = __floats2half2_rn(v.x, v.y);
            ((__half2*)g_a1)[2 * f + 1] = __floats2half2_rn(v.z, v.w);
        }
    }
}

// ---------------- fused GEMM (fp16 mma, fp32 accumulate) — R5 verbatim ------
// MODE 0: gate_up (K=2048) + silu*up -> g_dn.  B rows interleaved gate/up.
// MODE 1: down    (K=1408) -> Out (fp32).
template <int MODE>
__global__ void __launch_bounds__(NT, 1)
moe_gemm(float* __restrict__ Out) {
    constexpr int K  = (MODE == 0) ? HID : ITR;          // in halves
    constexpr int KT = K / BK;                           // 32 / 22
    constexpr int NWROWS = (MODE == 0) ? 2 * ITR : HID;

    extern __shared__ float sm[];
    const uint32_t sb = s2u(sm);
    const int tid = threadIdx.x, wid = tid >> 5, lane = tid & 31;
    const int g = lane >> 2, tg = lane & 3;
    const int e = blockIdx.z, m0 = blockIdx.y * BM, nb = blockIdx.x;

    const __half* Ag = ((MODE == 0) ? g_a1 : g_dn) + ((size_t)e * MPE + m0) * K;
    const __half* Bg = ((MODE == 0) ? g_w1 : g_w2) + ((size_t)e * NWROWS + (size_t)nb * BNR) * K;

    // cp.async: 16B chunks (8 halves); 8 chunks per 64-half row
    auto issue = [&](int t) {
        const int buf = t & 1;
        const int k0 = t * BK;
        const uint32_t abase = sb + (uint32_t)(buf * AST) * 4;
        const uint32_t bbase = sb + (uint32_t)(2 * AST + buf * BST) * 4;
        #pragma unroll
        for (int i = 0; i < 2; i++) {                // A: 1024 chunks
            int ci = tid + i * NT;
            int r = ci >> 3, c = ci & 7;
            cp16(abase + (uint32_t)r * (SST * 4) + c * 16, Ag + (size_t)r * K + k0 + c * 8);
        }
        #pragma unroll
        for (int i = 0; i < 4; i++) {                // B: 2048 chunks
            int ci = tid + i * NT;
            int r = ci >> 3, c = ci & 7;
            cp16(bbase + (uint32_t)r * (SST * 4) + c * 16, Bg + (size_t)r * K + k0 + c * 8);
        }
    };

    float acc[4][4][4];
    #pragma unroll
    for (int a = 0; a < 4; a++)
        #pragma unroll
        for (int b = 0; b < 4; b++)
            #pragma unroll
            for (int c = 0; c < 4; c++) acc[a][b][c] = 0.f;

    const int wm = (wid >> 3) * 64;   // warp m-offset (0/64)
    const int wn = (wid & 7) * 32;    // warp n-offset in B rows (0..224)

    auto compute = [&](int buf) {
        const uint32_t* As = (const uint32_t*)sm + buf * AST;
        const uint32_t* Bs = (const uint32_t*)sm + 2 * AST + buf * BST;
        #pragma unroll
        for (int ks = 0; ks < 4; ks++) {             // k16 steps (8 words each)
            uint32_t af[4][4], bf[4][2];
            #pragma unroll
            for (int mi = 0; mi < 4; mi++) {
                const uint32_t* p0 = As + (wm + mi * 16 + g) * SST + ks * 8 + tg;
                const uint32_t* p1 = p0 + 8 * SST;
                af[mi][0] = p0[0]; af[mi][1] = p1[0]; af[mi][2] = p0[4]; af[mi][3] = p1[4];
            }
            #pragma unroll
            for (int ni = 0; ni < 4; ni++) {
                const uint32_t* p = Bs + (wn + ni * 8 + g) * SST + ks * 8 + tg;
                bf[ni][0] = p[0]; bf[ni][1] = p[4];
            }
            #pragma unroll
            for (int mi = 0; mi < 4; mi++)
                #pragma unroll
                for (int ni = 0; ni < 4; ni++)
                    mma16(acc[mi][ni], af[mi], bf[ni]);
        }
    };

    // ---- 2-stage pipeline (R5) ----
    issue(0);
    asm volatile("cp.async.commit_group;" ::: "memory");
    for (int t = 0; t < KT; t++) {
        asm volatile("cp.async.wait_group 0;" ::: "memory");
        __syncthreads();
        if (t + 1 < KT) {
            issue(t + 1);
            asm volatile("cp.async.commit_group;" ::: "memory");
        }
        compute(t & 1);
    }

    // ---- epilogue ----
    if (MODE == 0) {
        // c0/c1 = (gate, up) of one out-col, rows g / g+8 via c2/c3
        const int ncol = nb * (BNR / 2) + (wn >> 1) + tg;   // + ni*4
        __half* D = g_dn + ((size_t)e * MPE + m0 + wm + g) * ITR + ncol;
        #pragma unroll
        for (int mi = 0; mi < 4; mi++) {
            __half* Dr0 = D + (size_t)(mi * 16) * ITR;
            __half* Dr1 = Dr0 + (size_t)8 * ITR;
            #pragma unroll
            for (int ni = 0; ni < 4; ni++) {
                float g0 = acc[mi][ni][0], u0 = acc[mi][ni][1];
                float g1 = acc[mi][ni][2], u1 = acc[mi][ni][3];
                Dr0[ni * 4] = __float2half_rn((g0 / (1.f + __expf(-g0))) * u0);
                Dr1[ni * 4] = __float2half_rn((g1 / (1.f + __expf(-g1))) * u1);
            }
        }
    } else {
        const int ncol = nb * BNR + wn + 2 * tg;            // + ni*8
        float* D = Out + ((size_t)e * MPE + m0 + wm + g) * HID + ncol;
        #pragma unroll
        for (int mi = 0; mi < 4; mi++) {
            float* Dr0 = D + (size_t)(mi * 16) * HID;
            float* Dr1 = Dr0 + (size_t)8 * HID;
            #pragma unroll
            for (int ni = 0; ni < 4; ni++) {
                float2 o0 = {acc[mi][ni][0], acc[mi][ni][1]};
                float2 o1 = {acc[mi][ni][2], acc[mi][ni][3]};
                *(float2*)(Dr0 + ni * 8) = o0;
                *(float2*)(Dr1 + ni * 8) = o1;
            }
        }
    }
}

extern "C" void kernel_launch(void* const* d_in, const int* in_sizes, int n_in,
                              void* d_out, int out_size) {
    const float* hs = (const float*)d_in[0];
    // d_in[1] = tokens_per_expert (uniform 1024/expert; matches reference reshape)
    const float* w1 = (const float*)d_in[2];
    const float* s1 = (const float*)d_in[3];
    const float* w2 = (const float*)d_in[4];
    const float* s2 = (const float*)d_in[5];
    float* out = (float*)d_out;

    cudaFuncSetAttribute(moe_gemm<0>, cudaFuncAttributeMaxDynamicSharedMemorySize, SMEM_BYTES);
    cudaFuncSetAttribute(moe_gemm<1>, cudaFuncAttributeMaxDynamicSharedMemorySize, SMEM_BYTES);

    pack_all<<<dim3(1536, 3), 256>>>(hs, w1, s1, w2, s2);
    // GEMM1 + silu*up: grid (2816/256, 8, 8) = (11, 8, 8)
    moe_gemm<0><<<dim3(2 * ITR / BNR, MPE / BM, E), NT, SMEM_BYTES>>>(nullptr);
    // GEMM2: grid (2048/256, 8, 8) = (8, 8, 8)
    moe_gemm<1><<<dim3(HID / BNR, MPE / BM, E), NT, SMEM_BYTES>>>(out);
}